// round 17
// baseline (speedup 1.0000x reference)
#include <cuda_runtime.h>
#include <math.h>
#include <cstdint>

#define T_STEPS 512
#define BATCH   128
#define IN_DIM  544
#define HID     512
#define G4H     2048
#define NACT    19
#define NCTA    128     // CTA = (batch-half, unit-group of 8)
#define TPB     256     // 8 warps: (mt2, np, split)
#define NU      8       // units per CTA (32 gate rows)

// LSTM SMEM: per-warp private double buffers + D + msm
#define PB_A     8704                         // A tile: 32 x 272B
#define PB_SLICE 13056                        // A + B(16x272)
#define PB_WARP  26112                        // 2 slices
#define SM_D     208896                       // 8 * PB_WARP
#define SM_MSM   (SM_D + 8704)                // D: 32 x 68 floats
#define SM_TOTAL (SM_MSM + 256 + 64)

// pre-GEMM (mma) SMEM
#define PM_STR   140
#define PM_A     0
#define PM_B     (64 * PM_STR * 4)
#define PM_BIAS  (PM_B + 128 * PM_STR * 4)
#define PM_TOTAL (PM_BIAS + 512)

// ---------------- scratch ----------------------------------------------------
__device__ float g_pre0[(size_t)T_STEPS * G4H * BATCH];     // [t][n][b]
__device__ float g_hidden[(size_t)T_STEPS * BATCH * HID];
__device__ float g_h0[2][BATCH][HID];                       // tf32-rounded h
__device__ float g_h1[2][BATCH][HID];
__device__ float g_wt0[G4H * HID];                          // tf32-rounded weights
__device__ float g_wt1i[G4H * HID];
__device__ float g_wt1h[G4H * HID];
__device__ unsigned int g_bar_count;

// ---------------- helpers ----------------------------------------------------
__device__ __forceinline__ uint32_t smem_u32(const void* p) {
    uint32_t a;
    asm("{ .reg .u64 t; cvta.to.shared.u64 t, %1; cvt.u32.u64 %0, t; }" : "=r"(a) : "l"(p));
    return a;
}
__device__ __forceinline__ float tf32r(float x) {
    uint32_t o; asm("cvt.rna.tf32.f32 %0, %1;" : "=r"(o) : "f"(x));
    return __uint_as_float(o);
}
__device__ __forceinline__ void ldsm4(uint32_t* r, uint32_t addr) {
    asm volatile("ldmatrix.sync.aligned.m8n8.x4.shared.b16 {%0,%1,%2,%3}, [%4];"
                 : "=r"(r[0]), "=r"(r[1]), "=r"(r[2]), "=r"(r[3]) : "r"(addr));
}
__device__ __forceinline__ void mma_tf32(float* d, const uint32_t* a, const uint32_t* b) {
    asm volatile("mma.sync.aligned.m16n8k8.row.col.f32.tf32.tf32.f32 "
                 "{%0,%1,%2,%3}, {%4,%5,%6,%7}, {%8,%9}, {%0,%1,%2,%3};"
                 : "+f"(d[0]), "+f"(d[1]), "+f"(d[2]), "+f"(d[3])
                 : "r"(a[0]), "r"(a[1]), "r"(a[2]), "r"(a[3]), "r"(b[0]), "r"(b[1]));
}
__device__ __forceinline__ void cp16cg(uint32_t d, const void* s) {
    asm volatile("cp.async.cg.shared.global [%0], [%1], 16;" :: "r"(d), "l"(s));
}
__device__ __forceinline__ void cp16ca(uint32_t d, const void* s) {
    asm volatile("cp.async.ca.shared.global [%0], [%1], 16;" :: "r"(d), "l"(s));
}
#define CP_COMMIT() asm volatile("cp.async.commit_group;" ::: "memory")
#define CP_WAIT1()  asm volatile("cp.async.wait_group 1;" ::: "memory")

__device__ __forceinline__ float sigmoidf_(float x) {
    return __fdividef(1.f, 1.f + __expf(-x));
}
__device__ __forceinline__ float tanhf_(float x) {
    float t = __expf(2.f * x);
    return 1.f - __fdividef(2.f, t + 1.f);
}

// ---------------- init / weight-round kernels --------------------------------
__global__ void init_kernel(const float* __restrict__ h0) {
    if (blockIdx.x == 0 && threadIdx.x == 0) g_bar_count = 0u;
    const int n = BATCH * HID;
    for (int i = blockIdx.x * blockDim.x + threadIdx.x; i < n; i += gridDim.x * blockDim.x) {
        (&g_h0[0][0][0])[i] = tf32r(h0[i]);
        (&g_h1[0][0][0])[i] = tf32r(h0[n + i]);
    }
}

__global__ void wt_kernel(const float* __restrict__ W0, const float* __restrict__ W1i,
                          const float* __restrict__ W1h) {
    const int n = G4H * HID;
    for (int i = blockIdx.x * blockDim.x + threadIdx.x; i < n; i += gridDim.x * blockDim.x) {
        g_wt0[i]  = tf32r(W0[i]);
        g_wt1i[i] = tf32r(W1i[i]);
        g_wt1h[i] = tf32r(W1h[i]);
    }
}

// ---------------- pre-GEMM via tf32 mma (unchanged) ---------------------------
__global__ void __launch_bounds__(256)
pre_mma_kernel(const float* __restrict__ X, const float* __restrict__ W,
               const float* __restrict__ bA, const float* __restrict__ bB)
{
    extern __shared__ char sm[];
    float* bias = (float*)(sm + PM_BIAS);
    float* D_s  = (float*)sm;

    const int tid  = threadIdx.x;
    const int w    = tid >> 5;
    const int lane = tid & 31;
    const int n0   = blockIdx.x * 128;
    const int row0 = blockIdx.y * 64;
    const int tt   = blockIdx.y >> 1;
    const int b0   = (blockIdx.y & 1) * 64;
    const int mt   = w >> 1;
    const int nh   = w & 1;

    if (tid < 128) bias[tid] = bA[n0 + tid] + bB[n0 + tid];

    const uint32_t sb = smem_u32(sm);
    const int st = lane >> 3;
    const uint32_t aA = sb + PM_A + (mt * 16 + (st & 1) * 8 + (lane & 7)) * 560 + (st >> 1) * 16;
    const uint32_t bBq = sb + PM_B + (nh * 64 + (st >> 1) * 8 + (lane & 7)) * 560 + (st & 1) * 16;

    float acc[32];
#pragma unroll
    for (int i = 0; i < 32; i++) acc[i] = 0.f;

    for (int kc = 0; kc < 4; kc++) {
        __syncthreads();
        {
            const int r = tid >> 2, q = tid & 3;
#pragma unroll
            for (int j = 0; j < 9; j++) {
                int c4 = j * 4 + q;
                if (c4 < 34) {
                    float4 v = __ldg((const float4*)&X[(size_t)(row0 + r) * IN_DIM + kc * 136 + c4 * 4]);
                    v.x = tf32r(v.x); v.y = tf32r(v.y); v.z = tf32r(v.z); v.w = tf32r(v.w);
                    *(float4*)(sm + PM_A + r * 560 + c4 * 16) = v;
                }
            }
        }
        {
            const int r = tid >> 1, q = tid & 1;
#pragma unroll
            for (int j = 0; j < 17; j++) {
                int c4 = j * 2 + q;
                float4 v = __ldg((const float4*)&W[(size_t)(n0 + r) * IN_DIM + kc * 136 + c4 * 4]);
                v.x = tf32r(v.x); v.y = tf32r(v.y); v.z = tf32r(v.z); v.w = tf32r(v.w);
                *(float4*)(sm + PM_B + r * 560 + c4 * 16) = v;
            }
        }
        __syncthreads();
#pragma unroll
        for (int ks = 0; ks < 17; ks++) {
            uint32_t af[4];
            ldsm4(af, aA + ks * 32);
#pragma unroll
            for (int nb = 0; nb < 4; nb++) {
                uint32_t bf[4];
                ldsm4(bf, bBq + nb * 16 * 560 + ks * 32);
                mma_tf32(acc + nb * 8 + 0, af, bf + 0);
                mma_tf32(acc + nb * 8 + 4, af, bf + 2);
            }
        }
    }

    __syncthreads();
    {
        const int r = lane >> 2, c2 = (lane & 3) * 2;
#pragma unroll
        for (int nb = 0; nb < 4; nb++) {
            const int nbase = nh * 64 + nb * 16;
            D_s[(nbase + c2 + 0) * 68 + mt * 16 + r]     = acc[nb * 8 + 0];
            D_s[(nbase + c2 + 1) * 68 + mt * 16 + r]     = acc[nb * 8 + 1];
            D_s[(nbase + c2 + 0) * 68 + mt * 16 + r + 8] = acc[nb * 8 + 2];
            D_s[(nbase + c2 + 1) * 68 + mt * 16 + r + 8] = acc[nb * 8 + 3];
            D_s[(nbase + 8 + c2 + 0) * 68 + mt * 16 + r]     = acc[nb * 8 + 4];
            D_s[(nbase + 8 + c2 + 1) * 68 + mt * 16 + r]     = acc[nb * 8 + 5];
            D_s[(nbase + 8 + c2 + 0) * 68 + mt * 16 + r + 8] = acc[nb * 8 + 6];
            D_s[(nbase + 8 + c2 + 1) * 68 + mt * 16 + r + 8] = acc[nb * 8 + 7];
        }
    }
    __syncthreads();
    {
        const int n = tid >> 1, mh = tid & 1;
        const float bs = bias[n];
        float* dst = &g_pre0[((size_t)tt * G4H + n0 + n) * BATCH + b0 + mh * 32];
        const float* src = &D_s[n * 68 + mh * 32];
#pragma unroll
        for (int s = 0; s < 8; s++) {
            float4 v = ((const float4*)src)[s];
            ((float4*)dst)[s] = make_float4(v.x + bs, v.y + bs, v.z + bs, v.w + bs);
        }
    }
}

// ---------------- persistent LSTM: warp-private pipelines ---------------------
__device__ __forceinline__ void grid_bar(unsigned int phase) {
    __threadfence();
    __syncthreads();
    if (threadIdx.x == 0) {
        atomicAdd(&g_bar_count, 1u);
        while (*(volatile unsigned int*)&g_bar_count < (unsigned)NCTA * phase) { __nanosleep(32); }
    }
    __syncthreads();
}

// stage one private k64 slice: A 32 rows, B 16 gate rows (32 lanes of one warp)
__device__ __forceinline__ void stage_slice(uint32_t sbuf,
                                            const float* __restrict__ A,
                                            const float* __restrict__ B,
                                            int k0, int arow0, int nrow0, int u0, int lane)
{
#pragma unroll
    for (int it = 0; it < 16; it++) {
        const int idx = it * 32 + lane;
        const int row = idx >> 4;
        const int kq  = (idx & 15) << 2;
        cp16cg(sbuf + row * 272 + kq * 4, &A[(size_t)(arow0 + row) * HID + k0 + kq]);
    }
#pragma unroll
    for (int it = 0; it < 8; it++) {
        const int idx = it * 32 + lane;
        const int row = idx >> 4;
        const int kq  = (idx & 15) << 2;
        const int r32 = nrow0 + row;
        const int grow = (r32 >> 3) * HID + u0 + (r32 & 7);
        cp16ca(sbuf + PB_A + row * 272 + kq * 4, &B[(size_t)grow * HID + k0 + kq]);
    }
}

// one k64 slice: warp tile m32 x n16
__device__ __forceinline__ void mma_slice(float* acc, uint32_t abase, uint32_t bbase)
{
#pragma unroll
    for (int ks = 0; ks < 8; ks++) {
        uint32_t a0[4], a1[4], bf[4];
        ldsm4(a0, abase + ks * 32);
        ldsm4(a1, abase + 16 * 272 + ks * 32);
        ldsm4(bf, bbase + ks * 32);
        mma_tf32(acc + 0,  a0, bf + 0);
        mma_tf32(acc + 4,  a0, bf + 2);
        mma_tf32(acc + 8,  a1, bf + 0);
        mma_tf32(acc + 12, a1, bf + 2);
    }
}

// frag -> D (n-stride 68): WRITE (ADD=0) or ACCUMULATE (ADD=1), scaled per m-row
template <int ADD>
__device__ __forceinline__ void frag_to_D(float* __restrict__ D, const float* __restrict__ acc,
                                          const float* __restrict__ scale2 /*[4] per row*/,
                                          int mt2, int np, int r, int c2)
{
#pragma unroll
    for (int ml = 0; ml < 2; ml++) {
#pragma unroll
        for (int nb = 0; nb < 2; nb++) {
            const int n = np * 16 + nb * 8 + c2;
            const int m = mt2 * 32 + ml * 16 + r;
            const float s0 = scale2[ml * 2 + 0];
            const float s1 = scale2[ml * 2 + 1];
            const float* a = acc + ml * 8 + nb * 4;
            if (ADD) {
                D[(n + 0) * 68 + m]     += s0 * a[0];
                D[(n + 1) * 68 + m]     += s0 * a[1];
                D[(n + 0) * 68 + m + 8] += s1 * a[2];
                D[(n + 1) * 68 + m + 8] += s1 * a[3];
            } else {
                D[(n + 0) * 68 + m]     = s0 * a[0];
                D[(n + 1) * 68 + m]     = s0 * a[1];
                D[(n + 0) * 68 + m + 8] = s1 * a[2];
                D[(n + 1) * 68 + m + 8] = s1 * a[3];
            }
        }
    }
}

__global__ void __launch_bounds__(TPB, 1)
lstm_kernel(const int* __restrict__ done,
            const float* __restrict__ c0_in,
            const float* __restrict__ b_ih1,
            const float* __restrict__ b_hh1,
            float* __restrict__ out_hT,
            float* __restrict__ out_cT)
{
    extern __shared__ char sm[];
    float* D   = (float*)(sm + SM_D);      // [32 n][68] gate sums
    float* msm = (float*)(sm + SM_MSM);    // 64 masks (CTA batch rows)

    const int tid  = threadIdx.x;
    const int w    = tid >> 5;
    const int lane = tid & 31;
    const int bh   = blockIdx.x & 1;
    const int B0   = bh * 64;
    const int u0   = (blockIdx.x >> 1) * NU;

    const int sp   = w & 1;            // split: L0 k-half / L1 gemm role (0=ih,1=hh)
    const int np   = (w >> 1) & 1;     // gate-row 16-group
    const int mt2  = w >> 2;           // batch 32-row group
    const int arow0 = B0 + mt2 * 32;
    const int nrow0 = np * 16;

    const uint32_t sb  = smem_u32(sm);
    const uint32_t pb0 = sb + w * PB_WARP;
    const uint32_t pb1 = pb0 + PB_SLICE;
    const int st = lane >> 3;
    const uint32_t aOffs = ((st & 1) * 8 + (lane & 7)) * 272 + (st >> 1) * 16;
    const uint32_t bOffs = PB_A + ((st >> 1) * 8 + (lane & 7)) * 272 + (st & 1) * 16;

    const int r  = lane >> 2;
    const int c2 = (lane & 3) * 2;

    const int bl = tid & 63;
    const int b  = B0 + bl;
    const int ug = (tid >> 6) * 2;

    float bias1[2][4];
#pragma unroll
    for (int j = 0; j < 2; j++)
#pragma unroll
        for (int g = 0; g < 4; g++) {
            int row = g * HID + u0 + ug + j;
            bias1[j][g] = b_ih1[row] + b_hh1[row];
        }

    float c0r[2], c1r[2];
#pragma unroll
    for (int j = 0; j < 2; j++) {
        c0r[j] = c0_in[(0 * BATCH + b) * HID + u0 + ug + j];
        c1r[j] = c0_in[(1 * BATCH + b) * HID + u0 + ug + j];
    }

    unsigned int phase = 0;
    const float onesc[4] = {1.f, 1.f, 1.f, 1.f};

    // bootstrap: L0(t=0) slices 0,1 into private bufs
    stage_slice(pb0, &g_h0[0][0][0], g_wt0, sp * 256 + 0 * 64, arow0, nrow0, u0, lane); CP_COMMIT();
    stage_slice(pb1, &g_h0[0][0][0], g_wt0, sp * 256 + 1 * 64, arow0, nrow0, u0, lane); CP_COMMIT();

    for (int t = 0; t < T_STEPS; t++) {
        const int p = t & 1;
        const float mk = 1.0f - (float)__ldg(&done[t * BATCH + b]);

        float pre[2][4];
#pragma unroll
        for (int j = 0; j < 2; j++)
#pragma unroll
            for (int g = 0; g < 4; g++)
                pre[j][g] = __ldcg(&g_pre0[((size_t)t * G4H + g * HID + u0 + ug + j) * BATCH + b]);

        if (tid < 64) msm[tid] = 1.0f - (float)__ldg(&done[t * BATCH + B0 + tid]);
        __syncthreads();   // msm ready; prior cell-update D reads done

        // ===== layer 0: D = mk * (h0 @ W_hh0^T), k-split across sp =====
        const float* hA0 = &g_h0[p][0][0];
        float acc[16];
#pragma unroll
        for (int i = 0; i < 16; i++) acc[i] = 0.f;

#pragma unroll
        for (int sl = 0; sl < 4; sl++) {
            CP_WAIT1();
            const uint32_t pb = (sl & 1) ? pb1 : pb0;
            mma_slice(acc, pb + aOffs, pb + bOffs);
            if (sl + 2 < 4)
                stage_slice(pb, hA0, g_wt0, sp * 256 + (sl + 2) * 64, arow0, nrow0, u0, lane);
            CP_COMMIT();
        }

        // merge k-halves into D with mask scale
        float mks[4];
#pragma unroll
        for (int ml = 0; ml < 2; ml++) {
            mks[ml * 2 + 0] = msm[mt2 * 32 + ml * 16 + r];
            mks[ml * 2 + 1] = msm[mt2 * 32 + ml * 16 + r + 8];
        }
        __syncthreads();
        if (sp == 0) frag_to_D<0>(D, acc, mks, mt2, np, r, c2);
        __syncthreads();
        if (sp == 1) frag_to_D<1>(D, acc, mks, mt2, np, r, c2);
        __syncthreads();

        // cell update 0
        {
#pragma unroll
            for (int j = 0; j < 2; j++) {
                const int u = ug + j;
                float gi = pre[j][0] + D[(0 * 8 + u) * 68 + bl];
                float gf = pre[j][1] + D[(1 * 8 + u) * 68 + bl];
                float gg = pre[j][2] + D[(2 * 8 + u) * 68 + bl];
                float go = pre[j][3] + D[(3 * 8 + u) * 68 + bl];
                float c  = fmaf(sigmoidf_(gf), c0r[j] * mk, sigmoidf_(gi) * tanhf_(gg));
                c0r[j]   = c;
                g_h0[p ^ 1][b][u0 + u] = tf32r(sigmoidf_(go) * tanhf_(c));
            }
        }

        grid_bar(++phase);

        // ===== layer 1: D = (h0_new @ W_ih1^T) + mk * (h1 @ W_hh1^T) =====
        const float* hA = (sp == 0) ? &g_h0[p ^ 1][0][0] : &g_h1[p][0][0];
        const float* wB = (sp == 0) ? g_wt1i : g_wt1h;
#pragma unroll
        for (int i = 0; i < 16; i++) acc[i] = 0.f;

        stage_slice(pb0, hA, wB, 0 * 64, arow0, nrow0, u0, lane); CP_COMMIT();
        stage_slice(pb1, hA, wB, 1 * 64, arow0, nrow0, u0, lane); CP_COMMIT();
#pragma unroll
        for (int sl = 0; sl < 8; sl++) {
            CP_WAIT1();
            const uint32_t pb = (sl & 1) ? pb1 : pb0;
            mma_slice(acc, pb + aOffs, pb + bOffs);
            if (sl + 2 < 8) {
                stage_slice(pb, hA, wB, (sl + 2) * 64, arow0, nrow0, u0, lane);
            } else if (t + 1 < T_STEPS) {
                // cross-step prefetch: L0(t+1) slices 0,1 (h0_new globally done: post-bar)
                stage_slice(pb, &g_h0[p ^ 1][0][0], g_wt0,
                            sp * 256 + (sl - 6) * 64, arow0, nrow0, u0, lane);
            }
            CP_COMMIT();
        }

        __syncthreads();
        if (sp == 0) frag_to_D<0>(D, acc, onesc, mt2, np, r, c2);      // ih, unscaled
        __syncthreads();
        if (sp == 1) frag_to_D<1>(D, acc, mks, mt2, np, r, c2);        // + mk*hh
        __syncthreads();

        // cell update 1
        {
#pragma unroll
            for (int j = 0; j < 2; j++) {
                const int u = ug + j;
                float gi = bias1[j][0] + D[(0 * 8 + u) * 68 + bl];
                float gf = bias1[j][1] + D[(1 * 8 + u) * 68 + bl];
                float gg = bias1[j][2] + D[(2 * 8 + u) * 68 + bl];
                float go = bias1[j][3] + D[(3 * 8 + u) * 68 + bl];
                float c  = fmaf(sigmoidf_(gf), c1r[j] * mk, sigmoidf_(gi) * tanhf_(gg));
                c1r[j]   = c;
                float h  = tf32r(sigmoidf_(go) * tanhf_(c));
                g_h1[p ^ 1][b][u0 + u] = h;
                g_hidden[((size_t)t * BATCH + b) * HID + u0 + u] = h;
            }
        }
        // next step's top sync orders D reuse; bar orders cross-CTA state
    }

    grid_bar(++phase);

#pragma unroll
    for (int j = 0; j < 2; j++) {
        out_cT[(0 * BATCH + b) * HID + u0 + ug + j] = c0r[j];
        out_cT[(1 * BATCH + b) * HID + u0 + ug + j] = c1r[j];
    }
    for (int i = blockIdx.x * TPB + tid; i < BATCH * HID; i += NCTA * TPB) {
        out_hT[i]               = __ldcg(&(&g_h0[0][0][0])[i]);
        out_hT[BATCH * HID + i] = __ldcg(&(&g_h1[0][0][0])[i]);
    }
}

// ---------------- actor/critic heads -----------------------------------------
__global__ void __launch_bounds__(256)
head_kernel(const float* __restrict__ Wa, const float* __restrict__ ba,
            const float* __restrict__ Wc, const float* __restrict__ bc,
            float* __restrict__ out)
{
    __shared__ float Ws[NACT * HID];
    __shared__ float bs[NACT];
    for (int i = threadIdx.x; i < 18 * HID; i += blockDim.x) Ws[i] = Wa[i];
    for (int i = threadIdx.x; i < HID; i += blockDim.x) Ws[18 * HID + i] = Wc[i];
    if (threadIdx.x < 18) bs[threadIdx.x] = ba[threadIdx.x];
    if (threadIdx.x == 18) bs[18] = bc[0];
    __syncthreads();

    const int warp = threadIdx.x >> 5;
    const int lane = threadIdx.x & 31;
    const size_t m = (size_t)blockIdx.x * 8 + warp;

    const float* hrow = &g_hidden[m * HID];
    float hv[16];
#pragma unroll
    for (int j = 0; j < 16; j++) hv[j] = hrow[lane + j * 32];

#pragma unroll
    for (int a = 0; a < NACT; a++) {
        float s = 0.f;
#pragma unroll
        for (int j = 0; j < 16; j++) s = fmaf(hv[j], Ws[a * HID + lane + j * 32], s);
#pragma unroll
        for (int off = 16; off > 0; off >>= 1) s += __shfl_xor_sync(0xffffffffu, s, off);
        if (lane == a) out[m * NACT + a] = s + bs[a];
    }
}

// ---------------- launch ------------------------------------------------------
extern "C" void kernel_launch(void* const* d_in, const int* in_sizes, int n_in,
                              void* d_out, int out_size)
{
    (void)in_sizes; (void)n_in; (void)out_size;
    const float* x     = (const float*)d_in[0];
    const int*   done  = (const int*)  d_in[1];
    const float* h0    = (const float*)d_in[2];
    const float* c0    = (const float*)d_in[3];
    const float* W_ih0 = (const float*)d_in[4];
    const float* W_hh0 = (const float*)d_in[5];
    const float* b_ih0 = (const float*)d_in[6];
    const float* b_hh0 = (const float*)d_in[7];
    const float* W_ih1 = (const float*)d_in[8];
    const float* W_hh1 = (const float*)d_in[9];
    const float* b_ih1 = (const float*)d_in[10];
    const float* b_hh1 = (const float*)d_in[11];
    const float* W_a   = (const float*)d_in[12];
    const float* b_a   = (const float*)d_in[13];
    const float* W_c   = (const float*)d_in[14];
    const float* b_c   = (const float*)d_in[15];

    float* out    = (float*)d_out;
    float* out_hT = out + (size_t)T_STEPS * BATCH * NACT;
    float* out_cT = out_hT + 2 * BATCH * HID;

    cudaFuncSetAttribute(lstm_kernel, cudaFuncAttributeMaxDynamicSharedMemorySize, SM_TOTAL);
    cudaFuncSetAttribute(pre_mma_kernel, cudaFuncAttributeMaxDynamicSharedMemorySize, PM_TOTAL);

    init_kernel<<<64, 256>>>(h0);
    wt_kernel<<<132, 256>>>(W_hh0, W_ih1, W_hh1);

    dim3 gg(G4H / 128, (T_STEPS * BATCH) / 64);
    pre_mma_kernel<<<gg, 256, PM_TOTAL>>>(x, W_ih0, b_ih0, b_hh0);

    lstm_kernel<<<NCTA, TPB, SM_TOTAL>>>(done, c0, b_ih1, b_hh1, out_hT, out_cT);

    head_kernel<<<(T_STEPS * BATCH) / 8, 256>>>(W_a, b_a, W_c, b_c, out);
}